// round 1
// baseline (speedup 1.0000x reference)
#include <cuda_runtime.h>
#include <cuda_bf16.h>
#include <cstdint>

#define NTOK   4096
#define DMODEL 1024
#define DFF    4096
#define NEXP   16
#define NPAIR  (NTOK*2)
#define WNB    64

// ---------------- scratch (device globals; no cudaMalloc allowed) ----------------
__device__ float g_ws_part[32*WNB];
__device__ float g_wscale[32];
__device__ int   g_cnt[NEXP];
__device__ int   g_off[NEXP+1];
__device__ float g_probs[(size_t)NEXP*NTOK];
__device__ int   g_fcnt[NEXP];
__device__ float g_rstd[NTOK];
__device__ int   g_pair_e[NPAIR];
__device__ int   g_pair_pos[NPAIR];
__device__ float g_pair_w[NPAIR];
__device__ int   g_slot_tok[NPAIR];
__device__ float g_slot_cw[NPAIR];
__device__ float g_ascale1[NPAIR];
__device__ float g_ascale2[NPAIR];
__device__ __nv_bfloat16 g_A1[(size_t)NPAIR*DMODEL];   // 16 MB
__device__ float         g_H [(size_t)NPAIR*DFF];      // 128 MB
__device__ __nv_bfloat16 g_A2[(size_t)NPAIR*DFF];      // 64 MB

// ---------------- helpers ----------------
__device__ __forceinline__ float warpSum(float v){
#pragma unroll
  for (int o=16;o>0;o>>=1) v += __shfl_xor_sync(0xffffffffu, v, o);
  return v;
}
__device__ __forceinline__ float warpMax(float v){
#pragma unroll
  for (int o=16;o>0;o>>=1) v = fmaxf(v, __shfl_xor_sync(0xffffffffu, v, o));
  return v;
}
__device__ __forceinline__ float gelu_tanh(float x){
  float x3 = x*x*x;
  return 0.5f*x*(1.f + tanhf(0.7978845608028654f*(x + 0.044715f*x3)));
}

// ---------------- K0: zero output + counters ----------------
__global__ void k0_init(float* __restrict__ out, int n){
  int i = blockIdx.x*blockDim.x + threadIdx.x;
  int stride = gridDim.x*blockDim.x;
  for (int j=i;j<n;j+=stride) out[j]=0.f;
  if (i < NEXP){ g_cnt[i]=0; g_fcnt[i]=0; }
}

// ---------------- K1: per-expert-matrix sum(|w|) partials ----------------
__global__ void k1_wsum(const float* __restrict__ w1, const float* __restrict__ w2){
  int m = blockIdx.y;  // 0..15 -> w1[e], 16..31 -> w2[e]
  const float* base = (m<16) ? (w1 + (size_t)m*DFF*DMODEL)
                             : (w2 + (size_t)(m-16)*(size_t)DMODEL*DFF);
  const int chunk = (DFF*DMODEL)/WNB;  // 65536 floats
  const float4* p = (const float4*)(base + (size_t)blockIdx.x*chunk);
  float s = 0.f;
  for (int i=threadIdx.x; i<chunk/4; i+=blockDim.x){
    float4 v = p[i];
    s += fabsf(v.x)+fabsf(v.y)+fabsf(v.z)+fabsf(v.w);
  }
  s = warpSum(s);
  __shared__ float sm[8];
  int lane=threadIdx.x&31, wid=threadIdx.x>>5;
  if (lane==0) sm[wid]=s;
  __syncthreads();
  if (threadIdx.x==0){
    float tot=0.f;
#pragma unroll
    for (int i=0;i<8;i++) tot+=sm[i];
    g_ws_part[m*WNB + blockIdx.x] = tot;
  }
}

// ---------------- K2: router (logits, softmax, top-2, rstd, aux partials) ---------
__global__ void k2_router(const float* __restrict__ x, const float* __restrict__ rw){
  int t = blockIdx.x;
  const float4* xr = (const float4*)(x + (size_t)t*DMODEL);
  int tid = threadIdx.x;   // 128 threads
  float lg[16];
#pragma unroll
  for (int e=0;e<16;e++) lg[e]=0.f;
  float ss = 0.f;
#pragma unroll
  for (int j=0;j<2;j++){
    float4 xv = xr[tid*2+j];
    ss += xv.x*xv.x + xv.y*xv.y + xv.z*xv.z + xv.w*xv.w;
#pragma unroll
    for (int e=0;e<16;e++){
      float4 rv = ((const float4*)(rw + (size_t)e*DMODEL))[tid*2+j];
      lg[e] += xv.x*rv.x + xv.y*rv.y + xv.z*rv.z + xv.w*rv.w;
    }
  }
#pragma unroll
  for (int e=0;e<16;e++) lg[e] = warpSum(lg[e]);
  ss = warpSum(ss);

  __shared__ float sh[4][17];
  int lane=tid&31, wid=tid>>5;
  if (lane==0){
#pragma unroll
    for (int e=0;e<16;e++) sh[wid][e]=lg[e];
    sh[wid][16]=ss;
  }
  __syncthreads();
  __shared__ float fin[17];
  if (tid<17) fin[tid] = sh[0][tid]+sh[1][tid]+sh[2][tid]+sh[3][tid];
  __syncthreads();
  __shared__ float spr[16];
  if (tid==0){
    g_rstd[t] = rsqrtf(fin[16]*(1.f/DMODEL) + 1e-6f);
    float mx = fin[0];
#pragma unroll
    for (int e=1;e<16;e++) mx = fmaxf(mx, fin[e]);
    float p[16]; float s=0.f;
#pragma unroll
    for (int e=0;e<16;e++){ p[e]=expf(fin[e]-mx); s+=p[e]; }
    float inv = 1.f/s;
#pragma unroll
    for (int e=0;e<16;e++){ p[e]*=inv; spr[e]=p[e]; }
    // top-2 on logits (same ordering as probs); ties -> lowest index, like lax.top_k
    int b1=0;
#pragma unroll
    for (int e=1;e<16;e++) if (fin[e]>fin[b1]) b1=e;
    int b2 = (b1==0)?1:0;
#pragma unroll
    for (int e=0;e<16;e++) if (e!=b1 && fin[e]>fin[b2]) b2=e;
    float ps = p[b1]+p[b2]+1e-8f;
    int pos1 = atomicAdd(&g_cnt[b1],1);
    int pos2 = atomicAdd(&g_cnt[b2],1);
    g_pair_e[2*t]=b1;   g_pair_pos[2*t]=pos1;   g_pair_w[2*t]=p[b1]/ps;
    g_pair_e[2*t+1]=b2; g_pair_pos[2*t+1]=pos2; g_pair_w[2*t+1]=p[b2]/ps;
    atomicAdd(&g_fcnt[b1],1);
    atomicAdd(&g_fcnt[b2],1);
  }
  __syncthreads();
  if (tid<16) g_probs[(size_t)tid*NTOK + t] = spr[tid];
}

// ---------------- K3: wscales, offsets, aux loss ----------------
__global__ void k3_finalize(float* __restrict__ out, long long out_size){
  int tid = threadIdx.x;  // 256
  if (tid < 32){
    float s = 0.f;
    for (int i=0;i<WNB;i++) s += g_ws_part[tid*WNB+i];
    float mean = s * (1.f/((float)DFF*(float)DMODEL));
    g_wscale[tid] = 1.f/fmaxf(mean, 1e-5f);
  }
  if (tid==0){
    int o=0;
#pragma unroll
    for (int e=0;e<NEXP;e++){ g_off[e]=o; o+=g_cnt[e]; }
    g_off[NEXP]=o;
  }
  __shared__ float paux[16][8];
  if (tid < 128){
    int e=tid>>3, j=tid&7;
    float s=0.f;
    const float* pr = g_probs + (size_t)e*NTOK + j*512;
    for (int i=0;i<512;i++) s += pr[i];
    paux[e][j]=s;
  }
  __syncthreads();
  if (tid==0 && out_size > (long long)NTOK*DMODEL){
    float aux=0.f;
#pragma unroll
    for (int e=0;e<16;e++){
      float pm=0.f;
#pragma unroll
      for (int j=0;j<8;j++) pm += paux[e][j];
      pm *= (1.f/NTOK);
      aux += ((float)g_fcnt[e]/(float)(NTOK*2)) * pm;
    }
    out[(size_t)NTOK*DMODEL] = (float)NEXP * aux;
  }
}

// ---------------- K4: layer-1 rmsnorm + act_quant into sorted slots -------------
__global__ void k4_quant1(const float* __restrict__ x, const float* __restrict__ g1){
  int p = blockIdx.x;
  int t = p>>1;
  int e = g_pair_e[p];
  int slot = g_off[e] + g_pair_pos[p];
  float r = g_rstd[t];
  const float4* xr = (const float4*)(x  + (size_t)t*DMODEL);
  const float4* gr = (const float4*)(g1 + (size_t)e*DMODEL);
  int tid = threadIdx.x;  // 128
  float v[8]; float am=0.f;
#pragma unroll
  for (int j=0;j<2;j++){
    float4 xv=xr[tid*2+j]; float4 gv=gr[tid*2+j];
    v[j*4+0]=xv.x*gv.x*r; v[j*4+1]=xv.y*gv.y*r;
    v[j*4+2]=xv.z*gv.z*r; v[j*4+3]=xv.w*gv.w*r;
#pragma unroll
    for (int k=0;k<4;k++) am = fmaxf(am, fabsf(v[j*4+k]));
  }
  am = warpMax(am);
  __shared__ float sm[4]; __shared__ float as_s;
  int lane=tid&31, wid=tid>>5;
  if (lane==0) sm[wid]=am;
  __syncthreads();
  if (tid==0){
    float m = fmaxf(fmaxf(sm[0],sm[1]), fmaxf(sm[2],sm[3]));
    as_s = 127.f/fmaxf(m, 1e-5f);
    g_ascale1[slot]=as_s;
    g_slot_tok[slot]=t;
    g_slot_cw[slot]=g_pair_w[p];
  }
  __syncthreads();
  float as = as_s;
  __nv_bfloat16* Ar = g_A1 + (size_t)slot*DMODEL;
#pragma unroll
  for (int j=0;j<8;j++){
    float q = fminf(127.f, fmaxf(-128.f, rintf(v[j]*as)));
    Ar[tid*8+j] = __float2bfloat16_rn(q);
  }
}

// ---------------- K6: layer-2 rmsnorm + act_quant ----------------
__global__ void k6_quant2(const float* __restrict__ g2){
  int slot = blockIdx.x;
  int e = 0;
#pragma unroll
  for (int i=1;i<NEXP;i++) if (slot >= g_off[i]) e = i;
  const float4* h4 = (const float4*)(g_H + (size_t)slot*DFF);
  const float4* g4 = (const float4*)(g2  + (size_t)e*DFF);
  int tid = threadIdx.x;  // 256
  float v[16]; float ss=0.f;
#pragma unroll
  for (int j=0;j<4;j++){
    float4 a = h4[tid*4+j];
    v[j*4+0]=a.x; v[j*4+1]=a.y; v[j*4+2]=a.z; v[j*4+3]=a.w;
    ss += a.x*a.x + a.y*a.y + a.z*a.z + a.w*a.w;
  }
  ss = warpSum(ss);
  __shared__ float sred[8];
  __shared__ float rstd_s, as_s;
  int lane=tid&31, wid=tid>>5;
  if (lane==0) sred[wid]=ss;
  __syncthreads();
  if (tid==0){
    float s=0.f;
#pragma unroll
    for (int i=0;i<8;i++) s+=sred[i];
    rstd_s = rsqrtf(s*(1.f/DFF) + 1e-6f);
  }
  __syncthreads();
  float r2 = rstd_s;
  float am = 0.f;
#pragma unroll
  for (int j=0;j<4;j++){
    float4 gg = g4[tid*4+j];
    v[j*4+0]*=gg.x*r2; v[j*4+1]*=gg.y*r2; v[j*4+2]*=gg.z*r2; v[j*4+3]*=gg.w*r2;
#pragma unroll
    for (int k=0;k<4;k++) am = fmaxf(am, fabsf(v[j*4+k]));
  }
  am = warpMax(am);
  if (lane==0) sred[wid]=am;
  __syncthreads();
  if (tid==0){
    float m=0.f;
#pragma unroll
    for (int i=0;i<8;i++) m=fmaxf(m,sred[i]);
    as_s = 127.f/fmaxf(m,1e-5f);
    g_ascale2[slot]=as_s;
  }
  __syncthreads();
  float as = as_s;
  __nv_bfloat16* Ar = g_A2 + (size_t)slot*DFF;
#pragma unroll
  for (int j=0;j<16;j++){
    float q = fminf(127.f, fmaxf(-128.f, rintf(v[j]*as)));
    Ar[tid*16+j] = __float2bfloat16_rn(q);
  }
}

// ---------------- GEMM: bf16 mma.sync m16n8k16, 128x128 CTA tile ----------------
// A: quantized int-valued bf16 activations (sorted by expert)
// B: fp32 weights, quantized to ternary bf16 on the fly
template<int KDIM, int NTOT, bool L1>
__global__ void __launch_bounds__(256) gemm_bit(const float* __restrict__ Wg,
                                               float* __restrict__ outp)
{
  __shared__ __nv_bfloat16 As[2][128][40];
  __shared__ __nv_bfloat16 Bs[2][128][40];

  const int e  = blockIdx.z;
  const int mt = blockIdx.x;
  const int nt = blockIdx.y;
  const int cnt = g_cnt[e];
  if (mt*128 >= cnt) return;
  const int off = g_off[e];
  const __nv_bfloat16* __restrict__ A = (L1 ? g_A1 : g_A2) + (size_t)off*KDIM;
  const float* __restrict__ W = Wg + ((size_t)e*NTOT + (size_t)nt*128)*(size_t)KDIM;
  const float ws = g_wscale[L1 ? e : 16+e];

  const int tid = threadIdx.x;
  const int lane = tid & 31, warp = tid >> 5;
  const int wm = warp >> 2, wn = warp & 3;   // 2 x 4 warp grid
  const int gq = lane >> 2, tq = lane & 3;

  float acc[4][4][4];
#pragma unroll
  for (int a=0;a<4;a++)
#pragma unroll
    for (int b=0;b<4;b++)
#pragma unroll
      for (int c=0;c<4;c++) acc[a][b][c]=0.f;

  const int lrow = tid >> 1;
  const int lseg = (tid & 1) * 16;
  const bool arow_ok = (mt*128 + lrow) < cnt;
  const __nv_bfloat16* Abase = A + (size_t)(mt*128 + lrow)*KDIM + lseg;
  const float* Wbase = W + (size_t)lrow*KDIM + lseg;

  uint4 areg[2];
  float4 wreg[4];

  auto loadg = [&](int k0){
    if (arow_ok){
      const uint4* p = (const uint4*)(Abase + k0);
      areg[0]=p[0]; areg[1]=p[1];
    } else {
      areg[0]=make_uint4(0,0,0,0); areg[1]=areg[0];
    }
    const float4* q = (const float4*)(Wbase + k0);
    wreg[0]=q[0]; wreg[1]=q[1]; wreg[2]=q[2]; wreg[3]=q[3];
  };
  auto stores = [&](int buf){
    uint4* sa = (uint4*)&As[buf][lrow][lseg];
    sa[0]=areg[0]; sa[1]=areg[1];
    uint32_t* sb = (uint32_t*)&Bs[buf][lrow][lseg];
#pragma unroll
    for (int j=0;j<4;j++){
      float4 w4 = wreg[j];
      float q0 = fminf(1.f, fmaxf(-1.f, rintf(w4.x*ws)));
      float q1 = fminf(1.f, fmaxf(-1.f, rintf(w4.y*ws)));
      float q2 = fminf(1.f, fmaxf(-1.f, rintf(w4.z*ws)));
      float q3 = fminf(1.f, fmaxf(-1.f, rintf(w4.w*ws)));
      __nv_bfloat162 p0 = __floats2bfloat162_rn(q0,q1);
      __nv_bfloat162 p1 = __floats2bfloat162_rn(q2,q3);
      sb[j*2+0] = *(uint32_t*)&p0;
      sb[j*2+1] = *(uint32_t*)&p1;
    }
  };
  auto compute = [&](int buf){
#pragma unroll
    for (int kk=0; kk<32; kk+=16){
      uint32_t af[4][4], bfr[4][2];
#pragma unroll
      for (int mi=0;mi<4;mi++){
        int r = wm*64 + mi*16 + gq;
        af[mi][0] = *(const uint32_t*)&As[buf][r  ][kk + tq*2];
        af[mi][1] = *(const uint32_t*)&As[buf][r+8][kk + tq*2];
        af[mi][2] = *(const uint32_t*)&As[buf][r  ][kk + tq*2 + 8];
        af[mi][3] = *(const uint32_t*)&As[buf][r+8][kk + tq*2 + 8];
      }
#pragma unroll
      for (int ni=0;ni<4;ni++){
        int c = wn*32 + ni*8 + gq;
        bfr[ni][0] = *(const uint32_t*)&Bs[buf][c][kk + tq*2];
        bfr[ni][1] = *(const uint32_t*)&Bs[buf][c][kk + tq*2 + 8];
      }
#pragma unroll
      for (int mi=0;mi<4;mi++)
#pragma unroll
        for (int ni=0;ni<4;ni++)
          asm volatile(
            "mma.sync.aligned.m16n8k16.row.col.f32.bf16.bf16.f32 "
            "{%0,%1,%2,%3}, {%4,%5,%6,%7}, {%8,%9}, {%0,%1,%2,%3};\n"
            : "+f"(acc[mi][ni][0]), "+f"(acc[mi][ni][1]),
              "+f"(acc[mi][ni][2]), "+f"(acc[mi][ni][3])
            : "r"(af[mi][0]), "r"(af[mi][1]), "r"(af[mi][2]), "r"(af[mi][3]),
              "r"(bfr[ni][0]), "r"(bfr[ni][1]));
    }
  };

  loadg(0);
  stores(0);
  const int KT = KDIM/32;
  for (int kt=0; kt<KT; kt++){
    __syncthreads();
    if (kt+1<KT) loadg((kt+1)*32);
    compute(kt&1);
    if (kt+1<KT) stores((kt+1)&1);
  }

  // ---------------- epilogue ----------------
  const int base_m = mt*128 + wm*64;
  const int base_n = nt*128 + wn*32;
#pragma unroll
  for (int mi=0;mi<4;mi++){
#pragma unroll
    for (int h=0;h<2;h++){
      int r = base_m + mi*16 + gq + h*8;
      if (r < cnt){
        int slot = off + r;
        if (L1){
          float dq = 1.f/(g_ascale1[slot]*ws);
          float* Hr = g_H + (size_t)slot*DFF;
#pragma unroll
          for (int ni=0;ni<4;ni++){
            int c = base_n + ni*8 + tq*2;
            float2 v;
            v.x = gelu_tanh(acc[mi][ni][h*2+0]*dq);
            v.y = gelu_tanh(acc[mi][ni][h*2+1]*dq);
            *(float2*)&Hr[c] = v;
          }
        } else {
          float coef = g_slot_cw[slot]/(g_ascale2[slot]*ws);
          float* orow = outp + (size_t)g_slot_tok[slot]*DMODEL;
#pragma unroll
          for (int ni=0;ni<4;ni++){
            int c = base_n + ni*8 + tq*2;
            atomicAdd(&orow[c],   acc[mi][ni][h*2+0]*coef);
            atomicAdd(&orow[c+1], acc[mi][ni][h*2+1]*coef);
          }
        }
      }
    }
  }
}

// ---------------- launch ----------------
extern "C" void kernel_launch(void* const* d_in, const int* in_sizes, int n_in,
                              void* d_out, int out_size){
  const float* x  = (const float*)d_in[0];
  const float* rw = (const float*)d_in[1];
  const float* w1 = (const float*)d_in[2];
  const float* g1 = (const float*)d_in[3];
  const float* w2 = (const float*)d_in[4];
  const float* g2 = (const float*)d_in[5];
  float* out = (float*)d_out;

  k0_init<<<1024,256>>>(out, NTOK*DMODEL);
  k1_wsum<<<dim3(WNB,32),256>>>(w1, w2);
  k2_router<<<NTOK,128>>>(x, rw);
  k3_finalize<<<1,256>>>(out, (long long)out_size);
  k4_quant1<<<NPAIR,128>>>(x, g1);
  gemm_bit<DMODEL,DFF,true><<<dim3(32,DFF/128,NEXP),256>>>(w1, nullptr);
  k6_quant2<<<NPAIR,256>>>(g2);
  gemm_bit<DFF,DMODEL,false><<<dim3(32,DMODEL/128,NEXP),256>>>(w2, out);
}